// round 1
// baseline (speedup 1.0000x reference)
#include <cuda_runtime.h>

// ---------------- problem constants ----------------
#define NX       51380224            // 32*128*112*112
#define NW       147456              // 128*128*3*3
#define HW       12544               // 112*112
#define WDIM     112
#define CIN      128
#define COUT     128
#define KK       9

#define GROUP    36
#define GPB      256                 // groups per block in quant_x
#define EPB      (GPB*GROUP)         // 9216 elems per block (divisible by 36)

// scratch (static device globals: allowed; no runtime allocation)
__device__ float g_xq[NX];                 // quantized input, f32
__device__ float g_wt[KK*CIN*COUT];        // quantized weight, transposed [k][ci][co]

// ---------------- BFP quantization helpers ----------------
__device__ __forceinline__ float bfp_q(float v, float inv_step, float step) {
    float q = rintf(v * inv_step);           // exact mul (power of 2), half-to-even like jnp.round
    q = fminf(fmaxf(q, -128.0f), 127.0f);    // clip(-(qmax+1), qmax)
    return q * step;
}

// Quantize x: block handles 9216 contiguous elems = 256 aligned groups.
__global__ void quant_x_kernel(const float* __restrict__ x) {
    __shared__ float sm[EPB];
    const long base = (long)blockIdx.x * EPB;
    for (int i = threadIdx.x; i < EPB; i += blockDim.x) {
        long gi = base + i;
        sm[i] = (gi < NX) ? x[gi] : 0.0f;     // zero-pad like jnp.pad
    }
    __syncthreads();

    const int t = threadIdx.x;
    const float* g = sm + t * GROUP;
    long obase = base + (long)t * GROUP;
    if (obase >= NX) return;
    long rem = NX - obase;
    int lim = rem < GROUP ? (int)rem : GROUP;

    float mx = 0.0f;
#pragma unroll
    for (int i = 0; i < GROUP; i++) mx = fmaxf(mx, fabsf(g[i]));

    if (mx > 0.0f) {
        int e = ilogbf(mx);                   // exact floor(log2(mx))
        float step = exp2f((float)(e - 7));
        float inv  = exp2f((float)(7 - e));
        for (int i = 0; i < lim; i++)
            g_xq[obase + i] = bfp_q(g[i], inv, step);
    } else {
        for (int i = 0; i < lim; i++) g_xq[obase + i] = 0.0f;
    }
}

// Quantize weight (4096 groups of 36, exact) and transpose to [k][ci][co].
__global__ void quant_w_kernel(const float* __restrict__ w) {
    int grp = blockIdx.x * blockDim.x + threadIdx.x;   // 0..4095
    if (grp >= NW / GROUP) return;
    const float* p = w + grp * GROUP;

    float mx = 0.0f;
#pragma unroll
    for (int i = 0; i < GROUP; i++) mx = fmaxf(mx, fabsf(p[i]));

    float step = 0.0f, inv = 0.0f;
    bool nz = (mx > 0.0f);
    if (nz) {
        int e = ilogbf(mx);
        step = exp2f((float)(e - 7));
        inv  = exp2f((float)(7 - e));
    }
#pragma unroll
    for (int i = 0; i < GROUP; i++) {
        int f  = grp * GROUP + i;                 // flat OIHW index
        int co = f / (CIN * KK);
        int r  = f % (CIN * KK);
        int ci = r / KK;
        int k  = r % KK;
        float q = nz ? bfp_q(p[i], inv, step) : 0.0f;
        g_wt[k * (CIN * COUT) + ci * COUT + co] = q;
    }
}

// ---------------- implicit-GEMM conv (fp32 baseline) ----------------
// Block: 128 Cout x 64 pixels (64 consecutive flat pixels; 12544%64==0 so one batch/block)
// 256 threads, each computes acc[8 co][4 px]. K = 9 kernel taps x 128 cin, smem chunks of 16.
__global__ void __launch_bounds__(256) conv_kernel(const float* __restrict__ bias,
                                                   float* __restrict__ out) {
    __shared__ float Asm[16][COUT];   // [ci_chunk][co]
    __shared__ float Bsm[16][64];     // [ci_chunk][px]

    const int tid  = threadIdx.x;
    const long p0  = (long)blockIdx.x * 64;
    const int b    = (int)(p0 / HW);
    const int s0   = (int)(p0 % HW);

    const int co0 = (tid >> 4) * 8;   // 0..120
    const int px0 = (tid & 15) * 4;   // 0..60

    float acc[8][4];
#pragma unroll
    for (int i = 0; i < 8; i++)
#pragma unroll
        for (int j = 0; j < 4; j++) acc[i][j] = 0.0f;

    // B-loader coords (each thread loads pixel lpx, rows lr, lr+4, lr+8, lr+12)
    const int lpx = tid & 63;
    const int lr  = tid >> 6;
    const int s   = s0 + lpx;
    const int h   = s / WDIM;
    const int w   = s % WDIM;
    const float* xb = g_xq + (long)b * (CIN * HW);

    for (int k = 0; k < KK; k++) {
        const int dh = k / 3 - 1, dw = k % 3 - 1;
        const int hh = h + dh,    ww = w + dw;
        const bool valid = ((unsigned)hh < WDIM) && ((unsigned)ww < WDIM);
        const int soff = hh * WDIM + ww;
        const float* wk = g_wt + k * (CIN * COUT);

        for (int ci0 = 0; ci0 < CIN; ci0 += 16) {
            // load A tile: 16x128, coalesced
#pragma unroll
            for (int j = 0; j < 8; j++) {
                int idx = tid + j * 256;
                Asm[idx >> 7][idx & 127] = wk[(ci0 + (idx >> 7)) * COUT + (idx & 127)];
            }
            // load B tile: 16x64
#pragma unroll
            for (int j = 0; j < 4; j++) {
                int ci = ci0 + lr + j * 4;
                Bsm[lr + j * 4][lpx] = valid ? xb[(long)ci * HW + soff] : 0.0f;
            }
            __syncthreads();

#pragma unroll
            for (int kk = 0; kk < 16; kk++) {
                const float4* A4 = reinterpret_cast<const float4*>(&Asm[kk][co0]);
                float4 a0 = A4[0], a1 = A4[1];
                float4 b4 = *reinterpret_cast<const float4*>(&Bsm[kk][px0]);
                float a[8] = {a0.x, a0.y, a0.z, a0.w, a1.x, a1.y, a1.z, a1.w};
                float bb[4] = {b4.x, b4.y, b4.z, b4.w};
#pragma unroll
                for (int i = 0; i < 8; i++)
#pragma unroll
                    for (int j = 0; j < 4; j++)
                        acc[i][j] = fmaf(a[i], bb[j], acc[i][j]);
            }
            __syncthreads();
        }
    }

    // epilogue: add bias, vectorized store (s0 mult of 64, px0 mult of 4 -> 16B aligned)
    float* ob = out + (long)b * (COUT * HW);
#pragma unroll
    for (int i = 0; i < 8; i++) {
        float bv = bias[co0 + i];
        float4 v = make_float4(acc[i][0] + bv, acc[i][1] + bv,
                               acc[i][2] + bv, acc[i][3] + bv);
        *reinterpret_cast<float4*>(&ob[(long)(co0 + i) * HW + s0 + px0]) = v;
    }
}

// ---------------- launch ----------------
extern "C" void kernel_launch(void* const* d_in, const int* in_sizes, int n_in,
                              void* d_out, int out_size) {
    const float* x    = (const float*)d_in[0];
    const float* wgt  = (const float*)d_in[1];
    const float* bias = (const float*)d_in[2];
    float* out = (float*)d_out;

    quant_x_kernel<<<(NX + EPB - 1) / EPB, 256>>>(x);
    quant_w_kernel<<<(NW / GROUP + 255) / 256, 256>>>(wgt);
    conv_kernel<<<(32 * HW) / 64, 256>>>(bias, out);
}

// round 2
// speedup vs baseline: 1.0001x; 1.0001x over previous
#include <cuda_runtime.h>

// ---------------- problem constants ----------------
#define NX       51380224            // 32*128*112*112
#define NW       147456              // 128*128*3*3
#define HW       12544               // 112*112
#define WDIM     112
#define CIN      128
#define COUT     128
#define KK       9

#define GROUP    36
#define GPB      256                 // groups per block in quant_x
#define EPB      (GPB*GROUP)         // 9216 elems per block (divisible by 36)

// scratch (static device globals: allowed; no runtime allocation)
__device__ float g_xq[NX];                 // quantized input, f32
__device__ float g_wt[KK*CIN*COUT];        // quantized weight, transposed [k][ci][co]

// ---------------- BFP quantization helpers ----------------
__device__ __forceinline__ float bfp_q(float v, float inv_step, float step) {
    float q = rintf(v * inv_step);           // exact mul (power of 2), half-to-even like jnp.round
    q = fminf(fmaxf(q, -128.0f), 127.0f);    // clip(-(qmax+1), qmax)
    return q * step;
}

// Quantize x: block handles 9216 contiguous elems = 256 aligned groups.
__global__ void quant_x_kernel(const float* __restrict__ x) {
    __shared__ float sm[EPB];
    const long base = (long)blockIdx.x * EPB;
    for (int i = threadIdx.x; i < EPB; i += blockDim.x) {
        long gi = base + i;
        sm[i] = (gi < NX) ? x[gi] : 0.0f;     // zero-pad like jnp.pad
    }
    __syncthreads();

    const int t = threadIdx.x;
    const float* g = sm + t * GROUP;
    long obase = base + (long)t * GROUP;
    if (obase >= NX) return;
    long rem = NX - obase;
    int lim = rem < GROUP ? (int)rem : GROUP;

    float mx = 0.0f;
#pragma unroll
    for (int i = 0; i < GROUP; i++) mx = fmaxf(mx, fabsf(g[i]));

    if (mx > 0.0f) {
        int e = ilogbf(mx);                   // exact floor(log2(mx))
        float step = exp2f((float)(e - 7));
        float inv  = exp2f((float)(7 - e));
        for (int i = 0; i < lim; i++)
            g_xq[obase + i] = bfp_q(g[i], inv, step);
    } else {
        for (int i = 0; i < lim; i++) g_xq[obase + i] = 0.0f;
    }
}

// Quantize weight (4096 groups of 36, exact) and transpose to [k][ci][co].
__global__ void quant_w_kernel(const float* __restrict__ w) {
    int grp = blockIdx.x * blockDim.x + threadIdx.x;   // 0..4095
    if (grp >= NW / GROUP) return;
    const float* p = w + grp * GROUP;

    float mx = 0.0f;
#pragma unroll
    for (int i = 0; i < GROUP; i++) mx = fmaxf(mx, fabsf(p[i]));

    float step = 0.0f, inv = 0.0f;
    bool nz = (mx > 0.0f);
    if (nz) {
        int e = ilogbf(mx);
        step = exp2f((float)(e - 7));
        inv  = exp2f((float)(7 - e));
    }
#pragma unroll
    for (int i = 0; i < GROUP; i++) {
        int f  = grp * GROUP + i;                 // flat OIHW index
        int co = f / (CIN * KK);
        int r  = f % (CIN * KK);
        int ci = r / KK;
        int k  = r % KK;
        float q = nz ? bfp_q(p[i], inv, step) : 0.0f;
        g_wt[k * (CIN * COUT) + ci * COUT + co] = q;
    }
}

// ---------------- implicit-GEMM conv (fp32 baseline) ----------------
// Block: 128 Cout x 64 pixels (64 consecutive flat pixels; 12544%64==0 so one batch/block)
// 256 threads, each computes acc[8 co][4 px]. K = 9 kernel taps x 128 cin, smem chunks of 16.
__global__ void __launch_bounds__(256) conv_kernel(const float* __restrict__ bias,
                                                   float* __restrict__ out) {
    __shared__ float Asm[16][COUT];   // [ci_chunk][co]
    __shared__ float Bsm[16][64];     // [ci_chunk][px]

    const int tid  = threadIdx.x;
    const long p0  = (long)blockIdx.x * 64;
    const int b    = (int)(p0 / HW);
    const int s0   = (int)(p0 % HW);

    const int co0 = (tid >> 4) * 8;   // 0..120
    const int px0 = (tid & 15) * 4;   // 0..60

    float acc[8][4];
#pragma unroll
    for (int i = 0; i < 8; i++)
#pragma unroll
        for (int j = 0; j < 4; j++) acc[i][j] = 0.0f;

    // B-loader coords (each thread loads pixel lpx, rows lr, lr+4, lr+8, lr+12)
    const int lpx = tid & 63;
    const int lr  = tid >> 6;
    const int s   = s0 + lpx;
    const int h   = s / WDIM;
    const int w   = s % WDIM;
    const float* xb = g_xq + (long)b * (CIN * HW);

    for (int k = 0; k < KK; k++) {
        const int dh = k / 3 - 1, dw = k % 3 - 1;
        const int hh = h + dh,    ww = w + dw;
        const bool valid = ((unsigned)hh < WDIM) && ((unsigned)ww < WDIM);
        const int soff = hh * WDIM + ww;
        const float* wk = g_wt + k * (CIN * COUT);

        for (int ci0 = 0; ci0 < CIN; ci0 += 16) {
            // load A tile: 16x128, coalesced
#pragma unroll
            for (int j = 0; j < 8; j++) {
                int idx = tid + j * 256;
                Asm[idx >> 7][idx & 127] = wk[(ci0 + (idx >> 7)) * COUT + (idx & 127)];
            }
            // load B tile: 16x64
#pragma unroll
            for (int j = 0; j < 4; j++) {
                int ci = ci0 + lr + j * 4;
                Bsm[lr + j * 4][lpx] = valid ? xb[(long)ci * HW + soff] : 0.0f;
            }
            __syncthreads();

#pragma unroll
            for (int kk = 0; kk < 16; kk++) {
                const float4* A4 = reinterpret_cast<const float4*>(&Asm[kk][co0]);
                float4 a0 = A4[0], a1 = A4[1];
                float4 b4 = *reinterpret_cast<const float4*>(&Bsm[kk][px0]);
                float a[8] = {a0.x, a0.y, a0.z, a0.w, a1.x, a1.y, a1.z, a1.w};
                float bb[4] = {b4.x, b4.y, b4.z, b4.w};
#pragma unroll
                for (int i = 0; i < 8; i++)
#pragma unroll
                    for (int j = 0; j < 4; j++)
                        acc[i][j] = fmaf(a[i], bb[j], acc[i][j]);
            }
            __syncthreads();
        }
    }

    // epilogue: add bias, vectorized store (s0 mult of 64, px0 mult of 4 -> 16B aligned)
    float* ob = out + (long)b * (COUT * HW);
#pragma unroll
    for (int i = 0; i < 8; i++) {
        float bv = bias[co0 + i];
        float4 v = make_float4(acc[i][0] + bv, acc[i][1] + bv,
                               acc[i][2] + bv, acc[i][3] + bv);
        *reinterpret_cast<float4*>(&ob[(long)(co0 + i) * HW + s0 + px0]) = v;
    }
}

// ---------------- launch ----------------
extern "C" void kernel_launch(void* const* d_in, const int* in_sizes, int n_in,
                              void* d_out, int out_size) {
    const float* x    = (const float*)d_in[0];
    const float* wgt  = (const float*)d_in[1];
    const float* bias = (const float*)d_in[2];
    float* out = (float*)d_out;

    quant_x_kernel<<<(NX + EPB - 1) / EPB, 256>>>(x);
    quant_w_kernel<<<(NW / GROUP + 255) / 256, 256>>>(wgt);
    conv_kernel<<<(32 * HW) / 64, 256>>>(bias, out);
}

// round 4
// speedup vs baseline: 4.7740x; 4.7735x over previous
#include <cuda_runtime.h>
#include <cuda_bf16.h>
#include <cstdint>

// ---------------- problem constants ----------------
#define NX       51380224            // 32*128*112*112
#define NW       147456              // 128*128*3*3
#define HW       12544               // 112*112
#define WDIM     112
#define CIN      128
#define COUT     128
#define KK       9

#define GROUP    36
#define EPB      9216                // elems per quant block (256 groups)

// scratch (static device globals)
__device__ __nv_bfloat16 g_xn[NX];             // quantized bf16, NCHW
__device__ __nv_bfloat16 g_xt[NX];             // quantized bf16, NHWC
__device__ __nv_bfloat16 g_w[KK * COUT * CIN]; // quantized bf16, [k][co][ci]

// ---------------- helpers ----------------
__device__ __forceinline__ uint32_t smem_u32(const void* p) {
    uint32_t a;
    asm("{ .reg .u64 t; cvta.to.shared.u64 t, %1; cvt.u32.u64 %0, t; }" : "=r"(a) : "l"(p));
    return a;
}

__device__ __forceinline__ void cp_async16(uint32_t dst, const void* src, uint32_t src_bytes) {
    asm volatile("cp.async.ca.shared.global [%0], [%1], 16, %2;"
                 :: "r"(dst), "l"(src), "r"(src_bytes) : "memory");
}
#define CP_COMMIT()  asm volatile("cp.async.commit_group;" ::: "memory")
#define CP_WAIT(n)   asm volatile("cp.async.wait_group %0;" :: "n"(n) : "memory")

__device__ __forceinline__ void ldmatrix_x4(uint32_t* r, uint32_t addr) {
    asm volatile("ldmatrix.sync.aligned.m8n8.x4.shared.b16 {%0,%1,%2,%3}, [%4];"
                 : "=r"(r[0]), "=r"(r[1]), "=r"(r[2]), "=r"(r[3]) : "r"(addr));
}

__device__ __forceinline__ void mma_bf16(float* d, const uint32_t* a, const uint32_t* b) {
    asm volatile(
        "mma.sync.aligned.m16n8k16.row.col.f32.bf16.bf16.f32 "
        "{%0,%1,%2,%3}, {%4,%5,%6,%7}, {%8,%9}, {%0,%1,%2,%3};"
        : "+f"(d[0]), "+f"(d[1]), "+f"(d[2]), "+f"(d[3])
        : "r"(a[0]), "r"(a[1]), "r"(a[2]), "r"(a[3]), "r"(b[0]), "r"(b[1]));
}

// ---------------- quantization ----------------
__device__ __forceinline__ float bfp_q(float v, float inv_step, float step) {
    float q = rintf(v * inv_step);            // exact (power-of-2 mul), half-to-even
    q = fminf(fmaxf(q, -128.0f), 127.0f);
    return q * step;                          // exact
}

// quant_x: block = 9216 contiguous elems = 256 groups; writes bf16 NCHW
__global__ void __launch_bounds__(256) quant_x_kernel(const float* __restrict__ x) {
    __shared__ float sm[EPB];
    const long base = (long)blockIdx.x * EPB;
    const int tid = threadIdx.x;

    const float4* xv = (const float4*)(x + base);
    float4* smv = (float4*)sm;
    if (base + EPB <= NX) {
#pragma unroll
        for (int i = 0; i < 9; i++) smv[tid + i * 256] = xv[tid + i * 256];
    } else {
        for (int i = 0; i < 9; i++) {
            int e4 = tid + i * 256;
            long e = base + (long)e4 * 4;
            float4 v = make_float4(0.f, 0.f, 0.f, 0.f);
            if (e + 3 < NX) v = xv[e4];
            else {
                float* vp = (float*)&v;
                for (int j = 0; j < 4; j++) if (e + j < NX) vp[j] = x[e + j];
            }
            smv[e4] = v;
        }
    }
    __syncthreads();

    const float* g = sm + tid * GROUP;
    float mx = 0.0f;
#pragma unroll
    for (int i = 0; i < GROUP; i++) mx = fmaxf(mx, fabsf(g[i]));

    // in-place repack: bf16 results into the front of this thread's own slot
    __nv_bfloat16* ob = (__nv_bfloat16*)((char*)sm + (size_t)tid * (GROUP * 4));
    if (mx > 0.0f) {
        int e = ilogbf(mx);
        float st  = exp2f((float)(e - 7));
        float inv = exp2f((float)(7 - e));
#pragma unroll
        for (int i = 0; i < GROUP; i++) ob[i] = __float2bfloat16(bfp_q(g[i], inv, st));
    } else {
#pragma unroll
        for (int i = 0; i < GROUP; i++) ob[i] = __float2bfloat16(0.0f);
    }
    __syncthreads();

    // copy out: 2304 uint2 units (8B = 4 bf16 each), 9 per thread, coalesced dst
    for (int j = 0; j < 9; j++) {
        int m = tid + j * 256;
        int t2 = m / 9, sub = m % 9;
        uint2 v = *(const uint2*)((char*)sm + (size_t)t2 * 144 + (size_t)sub * 8);
        long e0 = base + (long)m * 4;
        if (e0 + 3 < NX) {
            *(uint2*)(g_xn + e0) = v;
        } else {
            const __nv_bfloat16* vp = (const __nv_bfloat16*)&v;
            for (int q = 0; q < 4; q++) if (e0 + q < NX) g_xn[e0 + q] = vp[q];
        }
    }
}

// quant_w: 4096 groups of 36 (exact); writes bf16 transposed [k][co][ci]
__global__ void quant_w_kernel(const float* __restrict__ w) {
    int grp = blockIdx.x * blockDim.x + threadIdx.x;
    if (grp >= NW / GROUP) return;
    const float* p = w + grp * GROUP;

    float mx = 0.0f;
#pragma unroll
    for (int i = 0; i < GROUP; i++) mx = fmaxf(mx, fabsf(p[i]));

    float st = 0.0f, inv = 0.0f;
    bool nz = (mx > 0.0f);
    if (nz) {
        int e = ilogbf(mx);
        st  = exp2f((float)(e - 7));
        inv = exp2f((float)(7 - e));
    }
#pragma unroll
    for (int i = 0; i < GROUP; i++) {
        int f  = grp * GROUP + i;                  // flat OIHW
        int co = f / (CIN * KK);
        int r  = f % (CIN * KK);
        int ci = r / KK;
        int k  = r % KK;
        float q = nz ? bfp_q(p[i], inv, st) : 0.0f;
        g_w[k * (COUT * CIN) + co * CIN + ci] = __float2bfloat16(q);
    }
}

// ---------------- NCHW -> NHWC bf16 transpose ----------------
__global__ void __launch_bounds__(256) transpose_x_kernel() {
    __shared__ __nv_bfloat16 sm[128 * 72];
    const int tid = threadIdx.x;
    const int blk = blockIdx.x;              // b*196 + ptile
    const int b = blk / 196;
    const int p0 = (blk % 196) * 64;

#pragma unroll
    for (int i = 0; i < 4; i++) {
        int u = tid + i * 256;
        int ci = u >> 3, seg = u & 7;
        uint4 v = *(const uint4*)(g_xn + ((long)(b * CIN + ci) * HW + p0 + seg * 8));
        int col = (seg * 8) ^ (((ci >> 3) & 7) << 3);
        *(uint4*)(&sm[ci * 72 + col]) = v;
    }
    __syncthreads();

#pragma unroll
    for (int i = 0; i < 4; i++) {
        int u = tid + i * 256;
        int px = u >> 4, s2 = u & 15;
        __nv_bfloat16 tmp[8];
        int col = px ^ ((s2 & 7) << 3);
#pragma unroll
        for (int j = 0; j < 8; j++) tmp[j] = sm[(s2 * 8 + j) * 72 + col];
        *(uint4*)(g_xt + ((long)(b * HW + p0 + px) * CIN + s2 * 8)) = *(const uint4*)tmp;
    }
}

// ---------------- HMMA implicit-GEMM conv ----------------
// CTA: 128 Cout x 128 flat pixels, 256 threads = 8 warps (2 M x 4 N).
// Warp tile 64(co) x 32(px). K = 9 taps x 128 ci = 36 chunks of 32.
// smem tiles: A[co 128][32 ci], B[px 128][32 ci], pitch 80B (conflict-free ldmatrix).
#define PITCH 80

__global__ void __launch_bounds__(256) conv_hmma_kernel(const float* __restrict__ bias,
                                                        float* __restrict__ out) {
    __shared__ __align__(16) char sA[2][128 * PITCH];
    __shared__ __align__(16) char sB[2][128 * PITCH];

    const int tid  = threadIdx.x;
    const int lane = tid & 31, wid = tid >> 5;
    const int wm = wid >> 2, wn = wid & 3;      // warp grid 2x4
    const int b  = blockIdx.x / 98;
    const int s0 = (blockIdx.x % 98) * 128;

    // loader mapping: thread -> (row, 2 chunks of 16B)
    const int lrow = tid >> 1;
    const int lc   = (tid & 1) * 2;             // 16B-chunk pair {lc, lc+1}
    const int px = s0 + lrow;
    const int h = px / WDIM, w = px % WDIM;
    const long xrow_base = (long)b * HW * CIN;  // NHWC base for this batch

    uint32_t dA[2], dB[2];
#pragma unroll
    for (int bb = 0; bb < 2; bb++) {
        dA[bb] = smem_u32(&sA[bb][lrow * PITCH + lc * 16]);
        dB[bb] = smem_u32(&sB[bb][lrow * PITCH + lc * 16]);
    }

    float acc[4][4][4];
#pragma unroll
    for (int i = 0; i < 4; i++)
#pragma unroll
        for (int j = 0; j < 4; j++)
#pragma unroll
            for (int q = 0; q < 4; q++) acc[i][j][q] = 0.0f;

    // issue loads for chunk c into buffer buf
    auto issue = [&](int c, int buf) {
        int t = c >> 2, q = c & 3;              // tap, ci-quarter
        const __nv_bfloat16* wsrc = g_w + t * (COUT * CIN) + lrow * CIN + q * 32 + lc * 8;
        cp_async16(dA[buf],      wsrc,     16u);
        cp_async16(dA[buf] + 16, wsrc + 8, 16u);
        int dh = t / 3 - 1, dw = t % 3 - 1;
        int hh = h + dh, ww = w + dw;
        uint32_t vb = ((unsigned)hh < WDIM && (unsigned)ww < WDIM) ? 16u : 0u;
        const __nv_bfloat16* xsrc =
            g_xt + xrow_base + ((long)(hh * WDIM + ww)) * CIN + q * 32 + lc * 8;
        cp_async16(dB[buf],      xsrc,     vb);
        cp_async16(dB[buf] + 16, xsrc + 8, vb);
        CP_COMMIT();
    };

    issue(0, 0);

    const uint32_t aBaseRow = (uint32_t)((wm * 64 + (lane & 15)) * PITCH + (lane >> 4) * 16);
    const uint32_t bBaseRow = (uint32_t)((wn * 32 + (lane & 7) + ((lane >> 4) << 3)) * PITCH
                                         + ((lane >> 3) & 1) * 16);

    for (int c = 0; c < 36; c++) {
        int buf = c & 1;
        if (c < 35) issue(c + 1, buf ^ 1);
        if (c < 35) { CP_WAIT(1); } else { CP_WAIT(0); }
        __syncthreads();

        uint32_t baseA = smem_u32(&sA[buf][0]) + aBaseRow;
        uint32_t baseB = smem_u32(&sB[buf][0]) + bBaseRow;
#pragma unroll
        for (int ks = 0; ks < 2; ks++) {
            uint32_t afr[4][4];
#pragma unroll
            for (int i = 0; i < 4; i++)
                ldmatrix_x4(afr[i], baseA + i * 16 * PITCH + ks * 32);
            uint32_t bfr[2][4];
#pragma unroll
            for (int jj = 0; jj < 2; jj++)
                ldmatrix_x4(bfr[jj], baseB + jj * 16 * PITCH + ks * 32);
#pragma unroll
            for (int i = 0; i < 4; i++)
#pragma unroll
                for (int j = 0; j < 4; j++)
                    mma_bf16(acc[i][j], afr[i], &bfr[j >> 1][(j & 1) * 2]);
        }
        __syncthreads();
    }

    // epilogue: acc[i][j]: rows co = wm*64+i*16+{lane>>2, +8}, cols px = wn*32+j*8+(lane&3)*2
    float* ob = out + (long)b * (COUT * HW) + s0;
#pragma unroll
    for (int i = 0; i < 4; i++) {
        int r0 = wm * 64 + i * 16 + (lane >> 2);
        int r1 = r0 + 8;
        float bv0 = __ldg(&bias[r0]);
        float bv1 = __ldg(&bias[r1]);
        float* p0 = ob + (long)r0 * HW;
        float* p1 = ob + (long)r1 * HW;
#pragma unroll
        for (int j = 0; j < 4; j++) {
            int col = wn * 32 + j * 8 + (lane & 3) * 2;
            *(float2*)(p0 + col) = make_float2(acc[i][j][0] + bv0, acc[i][j][1] + bv0);
            *(float2*)(p1 + col) = make_float2(acc[i][j][2] + bv1, acc[i][j][3] + bv1);
        }
    }
}

// ---------------- launch ----------------
extern "C" void kernel_launch(void* const* d_in, const int* in_sizes, int n_in,
                              void* d_out, int out_size) {
    const float* x    = (const float*)d_in[0];
    const float* wgt  = (const float*)d_in[1];
    const float* bias = (const float*)d_in[2];
    float* out = (float*)d_out;

    quant_x_kernel<<<(NX + EPB - 1) / EPB, 256>>>(x);
    quant_w_kernel<<<(NW / GROUP + 255) / 256, 256>>>(wgt);
    transpose_x_kernel<<<32 * 196, 256>>>();
    conv_hmma_kernel<<<32 * 98, 256>>>(bias, out);
}